// round 7
// baseline (speedup 1.0000x reference)
#include <cuda_runtime.h>
#include <math.h>

#define NB 16
#define NPIX (512*512)
#define NP 10
#define NSLOT 30
#define EPS 1e-5f
#define LOG2E 1.4426950408889634f

// single-wave geometry: 16 batches x 37 blocks = 592 = 148 SMs x 4 blocks
#define BPB 37
#define THREADS 256
#define NWARP (THREADS/32)
#define GPB (NPIX/4)
#define FSTRIDE (BPB*THREADS)        // 9472
#define FITERS 7                     // ceil(65536/9472)
#define STAGES 3

typedef unsigned long long ull;

// ---- scratch (graph-capture safe device globals) ----
__device__ __align__(16) float g_fast[NB][BPB][12];
__device__ int   g_cnt[NB];                      // fast tickets (self-reset)
__device__ float g_part[NB][BPB][NSLOT][3];      // generic partials
__device__ int   g_cnt2[NB];                     // generic tickets

// ---------------- packed f32x2 helpers ----------------
__device__ __forceinline__ ull PK(float lo, float hi) {
    ull r; asm("mov.b64 %0,{%1,%2};" : "=l"(r) : "f"(lo), "f"(hi)); return r;
}
__device__ __forceinline__ void UPK(float& lo, float& hi, ull v) {
    asm("mov.b64 {%0,%1},%2;" : "=f"(lo), "=f"(hi) : "l"(v));
}
__device__ __forceinline__ ull ADD2(ull a, ull b) {
    ull r; asm("add.rn.f32x2 %0,%1,%2;" : "=l"(r) : "l"(a), "l"(b)); return r;
}
__device__ __forceinline__ ull MUL2(ull a, ull b) {
    ull r; asm("mul.rn.f32x2 %0,%1,%2;" : "=l"(r) : "l"(a), "l"(b)); return r;
}
__device__ __forceinline__ ull FMA2(ull a, ull b, ull c) {
    ull r; asm("fma.rn.f32x2 %0,%1,%2,%3;" : "=l"(r) : "l"(a), "l"(b), "l"(c)); return r;
}
__device__ __forceinline__ float ex2f(float a) {
    float r; asm("ex2.approx.f32 %0, %1;" : "=f"(r) : "f"(a)); return r;
}

// ---------------- cp.async helpers ----------------
__device__ __forceinline__ unsigned s2u(const void* p) {
    return (unsigned)__cvta_generic_to_shared(p);
}
#define CPASYNC16(dst, src) \
    asm volatile("cp.async.cg.shared.global [%0], [%1], 16;" :: "r"(dst), "l"(src))
#define CPCOMMIT() asm volatile("cp.async.commit_group;")
#define CPWAIT1()  asm volatile("cp.async.wait_group 1;")

__device__ __forceinline__ int fast_coeffs(
    const float* __restrict__ qp, const float* __restrict__ ln1w,
    const float* __restrict__ ln1b, const float* __restrict__ Wk,
    const float* __restrict__ bk, float g0[3], float g1[3])
{
    int ok = 1;
    #pragma unroll
    for (int h = 0; h < 3; h++) {
        float q = qp[h];
        #pragma unroll
        for (int j = 1; j < NP; j++) ok &= (qp[j*3 + h] == q);
        float F[3]; float n2 = 0.f;
        #pragma unroll
        for (int c = 0; c < 3; c++) {
            F[c] = q * Wk[h*3+c] * ln1w[c];
            n2 += F[c] * F[c];
        }
        float r = 1.7320509f * sqrtf(n2);
        ok &= (2.f * r <= 60.f);
        g0[h] = (F[0] - F[2]) * LOG2E;
        g1[h] = (F[1] - F[2]) * LOG2E;
    }
    return ok;
}

// shared epilogue: o[3] -> Wp -> LN2 -> SiLU FFN -> heads; writes row qi of batch b
__device__ __forceinline__ void epilogue_one(
    int b, int qi, float o0, float o1, float o2,
    const float* __restrict__ Wp, const float* __restrict__ bp,
    const float* __restrict__ ln2w, const float* __restrict__ ln2b,
    const float* __restrict__ W1, const float* __restrict__ b1,
    const float* __restrict__ W2, const float* __restrict__ b2,
    const float* __restrict__ Wg, const float* __restrict__ bg,
    const float* __restrict__ Wc, const float* __restrict__ bc,
    const float* __restrict__ gb, const float* __restrict__ cb,
    float* __restrict__ out)
{
    float op[3];
    #pragma unroll
    for (int e = 0; e < 3; e++)
        op[e] = bp[e] + o0*Wp[e*3+0] + o1*Wp[e*3+1] + o2*Wp[e*3+2];

    float mu = (op[0] + op[1] + op[2]) * (1.0f/3.0f);
    float d0 = op[0]-mu, d1 = op[1]-mu, d2 = op[2]-mu;
    float var = (d0*d0 + d1*d1 + d2*d2) * (1.0f/3.0f);
    float inv = rsqrtf(var + EPS);
    float h2[3];
    h2[0] = d0*inv*ln2w[0] + ln2b[0];
    h2[1] = d1*inv*ln2w[1] + ln2b[1];
    h2[2] = d2*inv*ln2w[2] + ln2b[2];

    float y[3] = { op[0] + b2[0], op[1] + b2[1], op[2] + b2[2] };
    #pragma unroll
    for (int f = 0; f < 12; f++) {
        float u = b1[f] + h2[0]*W1[f*3+0] + h2[1]*W1[f*3+1] + h2[2]*W1[f*3+2];
        float su = u / (1.0f + __expf(-u));
        y[0] += su * W2[0*12 + f];
        y[1] += su * W2[1*12 + f];
        y[2] += su * W2[2*12 + f];
    }
    if (qi == 0) {
        out[b] = bg[0] + gb[0] + y[0]*Wg[0] + y[1]*Wg[1] + y[2]*Wg[2];
    } else {
        int p = qi - 1;
        out[NB + b*9 + p] = bc[0] + y[0]*Wc[0] + y[1]*Wc[1] + y[2]*Wc[2] + cb[p];
    }
}

// ---------------------------------------------------------------------------
// GENERIC cold path (never runs on the real input; __noinline__ keeps its
// register/local pressure out of the hot path). Exact online-softmax.
// ---------------------------------------------------------------------------
__device__ __noinline__ void generic_path(
    const float* __restrict__ x, const float* __restrict__ qp,
    const float* __restrict__ ln1w, const float* __restrict__ ln1b,
    const float* __restrict__ Wk, const float* __restrict__ bk,
    const float* __restrict__ Wv, const float* __restrict__ bv,
    const float* __restrict__ Wp, const float* __restrict__ bp,
    const float* __restrict__ ln2w, const float* __restrict__ ln2b,
    const float* __restrict__ W1, const float* __restrict__ b1,
    const float* __restrict__ W2, const float* __restrict__ b2,
    const float* __restrict__ Wg, const float* __restrict__ bg,
    const float* __restrict__ Wc, const float* __restrict__ bc,
    const float* __restrict__ gb, const float* __restrict__ cb,
    float* __restrict__ out)
{
    __shared__ float s_da[3][NP];
    __shared__ int   s_cnt[3];
    __shared__ float s_redg[NWARP][NSLOT][3];
    __shared__ float s_comb[NSLOT][2];
    __shared__ int   s_wing;

    const int b    = blockIdx.x / BPB;
    const int blk  = blockIdx.x - b * BPB;
    const int t    = threadIdx.x;
    const int lane = t & 31;
    const int warp = t >> 5;

    if (t == 0) {
        for (int h = 0; h < 3; h++) {
            int cnt = 0;
            for (int j = 0; j < NP; j++) {
                float v = qp[j*3 + h];
                int f = -1;
                for (int c = 0; c < cnt; c++) if (s_da[h][c] == v) { f = c; break; }
                if (f < 0) { s_da[h][cnt] = v; cnt++; }
            }
            for (int j = cnt; j < NP; j++) s_da[h][j] = 0.0f;
            s_cnt[h] = cnt;
        }
    }
    __syncthreads();

    float Ak[3][3], Bk[3], Av[3][3], Bv[3];
    #pragma unroll
    for (int h = 0; h < 3; h++) {
        float sk = bk[h], sv0 = bv[h];
        #pragma unroll
        for (int c = 0; c < 3; c++) {
            float wkv = Wk[h*3+c], wvv = Wv[h*3+c];
            Ak[h][c] = wkv * ln1w[c];
            Av[h][c] = wvv * ln1w[c];
            sk  += wkv * ln1b[c];
            sv0 += wvv * ln1b[c];
        }
        Bk[h] = sk; Bv[h] = sv0;
    }

    float da[3][NP]; int cnt[3];
    #pragma unroll
    for (int h = 0; h < 3; h++) {
        cnt[h] = s_cnt[h];
        #pragma unroll
        for (int j = 0; j < NP; j++) da[h][j] = s_da[h][j];
    }

    float am[3][NP], as[3][NP], avv[3][NP];
    #pragma unroll
    for (int h = 0; h < 3; h++)
        #pragma unroll
        for (int j = 0; j < NP; j++) { am[h][j] = -1e30f; as[h][j] = 0.f; avv[h][j] = 0.f; }

    const float4* p0 = (const float4*)(x + (size_t)b * 3 * NPIX);
    const float4* p1 = p0 + GPB;
    const float4* p2 = p0 + 2*GPB;
    const int gbase = blk*THREADS + t;

    for (int it = 0; it < FITERS; it++) {
        int g = gbase + it*FSTRIDE;
        if (g >= GPB) break;
        float4 r0 = p0[g], r1 = p1[g], r2 = p2[g];
        float c0[4] = {r0.x, r0.y, r0.z, r0.w};
        float c1[4] = {r1.x, r1.y, r1.z, r1.w};
        float c2[4] = {r2.x, r2.y, r2.z, r2.w};
        #pragma unroll
        for (int e = 0; e < 4; e++) {
            float x0 = c0[e], x1 = c1[e], x2 = c2[e];
            float mu  = (x0 + x1 + x2) * (1.0f/3.0f);
            float d0 = x0 - mu, d1 = x1 - mu, d2 = x2 - mu;
            float var = (d0*d0 + d1*d1 + d2*d2) * (1.0f/3.0f);
            float inv = rsqrtf(var + EPS);
            float kh[3], vh[3];
            #pragma unroll
            for (int h = 0; h < 3; h++) {
                kh[h] = fmaf(inv, d0*Ak[h][0] + d1*Ak[h][1] + d2*Ak[h][2], Bk[h]);
                vh[h] = fmaf(inv, d0*Av[h][0] + d1*Av[h][1] + d2*Av[h][2], Bv[h]);
            }
            #pragma unroll
            for (int h = 0; h < 3; h++) {
                #pragma unroll
                for (int j = 0; j < NP; j++) {
                    if (j >= cnt[h]) break;
                    float l = da[h][j] * kh[h];
                    if (l > am[h][j]) {
                        float cc = __expf(am[h][j] - l);
                        as[h][j]  = fmaf(as[h][j], cc, 1.0f);
                        avv[h][j] = fmaf(avv[h][j], cc, vh[h]);
                        am[h][j] = l;
                    } else {
                        float e2 = __expf(l - am[h][j]);
                        as[h][j] += e2;
                        avv[h][j] = fmaf(e2, vh[h], avv[h][j]);
                    }
                }
            }
        }
    }

    #pragma unroll
    for (int h = 0; h < 3; h++) {
        #pragma unroll
        for (int j = 0; j < NP; j++) {
            float m = am[h][j];
            float M = m;
            #pragma unroll
            for (int off = 16; off > 0; off >>= 1)
                M = fmaxf(M, __shfl_xor_sync(0xffffffffu, M, off));
            float f  = __expf(m - M);
            float s  = as[h][j] * f;
            float sv = avv[h][j] * f;
            #pragma unroll
            for (int off = 16; off > 0; off >>= 1) {
                s  += __shfl_xor_sync(0xffffffffu, s,  off);
                sv += __shfl_xor_sync(0xffffffffu, sv, off);
            }
            if (lane == 0) {
                s_redg[warp][h*NP+j][0] = M;
                s_redg[warp][h*NP+j][1] = s;
                s_redg[warp][h*NP+j][2] = sv;
            }
        }
    }
    __syncthreads();
    if (t < NSLOT) {
        float M = -1e30f;
        #pragma unroll
        for (int w = 0; w < NWARP; w++) M = fmaxf(M, s_redg[w][t][0]);
        float s = 0.f, sv = 0.f;
        #pragma unroll
        for (int w = 0; w < NWARP; w++) {
            float f = __expf(s_redg[w][t][0] - M);
            s  = fmaf(s_redg[w][t][1], f, s);
            sv = fmaf(s_redg[w][t][2], f, sv);
        }
        g_part[b][blk][t][0] = M;
        g_part[b][blk][t][1] = s;
        g_part[b][blk][t][2] = sv;
    }
    __threadfence();
    if (t == 0) s_wing = (atomicAdd(&g_cnt2[b], 1) == BPB - 1);
    __syncthreads();
    if (!s_wing) return;

    for (int slot = warp; slot < NSLOT; slot += NWARP) {
        float m = g_part[b][lane][slot][0];
        float s = g_part[b][lane][slot][1];
        float sv = g_part[b][lane][slot][2];
        if (lane + 32 < BPB) {
            float m2 = g_part[b][lane+32][slot][0];
            float s2 = g_part[b][lane+32][slot][1];
            float v2 = g_part[b][lane+32][slot][2];
            float mm = fmaxf(m, m2);
            float f1 = __expf(m - mm), f2 = __expf(m2 - mm);
            s  = s*f1 + s2*f2;
            sv = sv*f1 + v2*f2;
            m = mm;
        }
        float M = m;
        #pragma unroll
        for (int off = 16; off > 0; off >>= 1)
            M = fmaxf(M, __shfl_xor_sync(0xffffffffu, M, off));
        float f = __expf(m - M);
        s *= f; sv *= f;
        #pragma unroll
        for (int off = 16; off > 0; off >>= 1) {
            s  += __shfl_xor_sync(0xffffffffu, s,  off);
            sv += __shfl_xor_sync(0xffffffffu, sv, off);
        }
        if (lane == 0) {
            s_comb[slot][0] = s;
            s_comb[slot][1] = sv;
        }
    }
    __syncthreads();

    if (t == 0) g_cnt2[b] = 0;
    if (t >= NP) return;
    int qi = t;

    float o[3];
    #pragma unroll
    for (int h = 0; h < 3; h++) {
        float list[NP]; int cnt2 = 0; int idx = 0;
        for (int j = 0; j <= qi; j++) {
            float v2 = qp[j*3 + h];
            int f = -1;
            for (int c = 0; c < cnt2; c++) if (list[c] == v2) { f = c; break; }
            if (f < 0) { list[cnt2] = v2; f = cnt2; cnt2++; }
            if (j == qi) idx = f;
        }
        o[h] = s_comb[h*NP + idx][1] / s_comb[h*NP + idx][0];
    }
    epilogue_one(b, qi, o[0], o[1], o[2], Wp, bp, ln2w, ln2b,
                 W1, b1, W2, b2, Wg, bg, Wc, bc, gb, cb, out);
}

// ---------------------------------------------------------------------------
// Single fused kernel: fast path = cp.async 3-stage smem pipeline + packed
// f32x2 math; last block per batch combines + epilogue. Generic cold branch.
// ---------------------------------------------------------------------------
__global__ void __launch_bounds__(THREADS, 4) k_all(
    const float* __restrict__ x,  const float* __restrict__ qp,
    const float* __restrict__ ln1w, const float* __restrict__ ln1b,
    const float* __restrict__ Wk, const float* __restrict__ bk,
    const float* __restrict__ Wv, const float* __restrict__ bv,
    const float* __restrict__ Wp, const float* __restrict__ bp,
    const float* __restrict__ ln2w, const float* __restrict__ ln2b,
    const float* __restrict__ W1, const float* __restrict__ b1,
    const float* __restrict__ W2, const float* __restrict__ b2,
    const float* __restrict__ Wg, const float* __restrict__ bg,
    const float* __restrict__ Wc, const float* __restrict__ bc,
    const float* __restrict__ gb, const float* __restrict__ cb,
    float* __restrict__ out)
{
    float g0s[3], g1s[3];
    if (!fast_coeffs(qp, ln1w, ln1b, Wk, bk, g0s, g1s)) {
        generic_path(x, qp, ln1w, ln1b, Wk, bk, Wv, bv, Wp, bp, ln2w, ln2b,
                     W1, b1, W2, b2, Wg, bg, Wc, bc, gb, cb, out);
        return;
    }

    // [channel][stage*THREADS + tid] : 3*3*256*16 = 36864 B
    __shared__ __align__(16) float4 sbuf[3][STAGES*THREADS];
    __shared__ float s_red[NWARP][12];
    __shared__ float s_o[3];
    __shared__ int   s_win;

    const int b    = blockIdx.x / BPB;
    const int blk  = blockIdx.x - b * BPB;
    const int t    = threadIdx.x;
    const int lane = t & 31;
    const int warp = t >> 5;

    ull G0[3], G1[3];
    #pragma unroll
    for (int h = 0; h < 3; h++) { G0[h] = PK(g0s[h], g0s[h]); G1[h] = PK(g1s[h], g1s[h]); }
    const ull nthird2 = PK(-1.0f/3.0f, -1.0f/3.0f);
    const ull twoth2  = PK( 2.0f/3.0f,  2.0f/3.0f);
    const ull eps2    = PK(EPS, EPS);

    ull S[3], T0[3], T1[3];
    #pragma unroll
    for (int h = 0; h < 3; h++) { S[h] = 0ull; T0[h] = 0ull; T1[h] = 0ull; }

    const float* xb = x + (size_t)b * 3 * NPIX;
    const float4* p0 = (const float4*)xb;
    const float4* p1 = p0 + GPB;
    const float4* p2 = p0 + 2*GPB;

    const int base = blk * THREADS + t;
    const unsigned sb0 = s2u(&sbuf[0][t]);
    const unsigned sb1 = s2u(&sbuf[1][t]);
    const unsigned sb2 = s2u(&sbuf[2][t]);

    // prologue: stages 0..STAGES-2
    #pragma unroll
    for (int s = 0; s < STAGES-1; s++) {
        int g = base + s*FSTRIDE;
        if (g < GPB) {
            unsigned off = (unsigned)(s*THREADS) * 16u;
            CPASYNC16(sb0 + off, p0 + g);
            CPASYNC16(sb1 + off, p1 + g);
            CPASYNC16(sb2 + off, p2 + g);
        }
        CPCOMMIT();
    }

    #pragma unroll
    for (int it = 0; it < FITERS; it++) {
        CPWAIT1();                       // stage 'it' is complete
        const int s = it % STAGES;
        const int g = base + it*FSTRIDE;
        if (g < GPB) {
            float4 a0 = sbuf[0][s*THREADS + t];
            float4 a1 = sbuf[1][s*THREADS + t];
            float4 a2 = sbuf[2][s*THREADS + t];
            #pragma unroll
            for (int pr = 0; pr < 2; pr++) {
                float xa = pr ? a0.z : a0.x, ya = pr ? a0.w : a0.y;
                float xb2 = pr ? a1.z : a1.x, yb = pr ? a1.w : a1.y;
                float xc = pr ? a2.z : a2.x, yc = pr ? a2.w : a2.y;
                ull c0 = PK(xa, ya), c1 = PK(xb2, yb), c2 = PK(xc, yc);
                ull sm = ADD2(ADD2(c0, c1), c2);
                ull nmu = MUL2(sm, nthird2);
                ull d0 = ADD2(c0, nmu);
                ull d1 = ADD2(c1, nmu);
                ull qq = MUL2(d0, d0);
                ull tq = FMA2(d1, d1, qq);
                ull t2 = FMA2(d0, d1, tq);
                ull vg = FMA2(t2, twoth2, eps2);
                float vl, vh; UPK(vl, vh, vg);
                ull inv2 = PK(rsqrtf(vl), rsqrtf(vh));
                ull u0 = MUL2(d0, inv2), u1 = MUL2(d1, inv2);
                #pragma unroll
                for (int h = 0; h < 3; h++) {
                    ull arg = FMA2(u1, G1[h], MUL2(u0, G0[h]));
                    float al, ah; UPK(al, ah, arg);
                    ull ee = PK(ex2f(al), ex2f(ah));
                    S[h]  = ADD2(S[h], ee);
                    T0[h] = FMA2(ee, u0, T0[h]);
                    T1[h] = FMA2(ee, u1, T1[h]);
                }
            }
        }
        // issue stage it+STAGES-1
        const int itn = it + STAGES - 1;
        if (itn < FITERS) {
            const int gn = base + itn*FSTRIDE;
            const int sn = itn % STAGES;
            if (gn < GPB) {
                unsigned off = (unsigned)(sn*THREADS) * 16u;
                CPASYNC16(sb0 + off, p0 + gn);
                CPASYNC16(sb1 + off, p1 + gn);
                CPASYNC16(sb2 + off, p2 + gn);
            }
            CPCOMMIT();
        }
    }

    float acc[12];
    #pragma unroll
    for (int h = 0; h < 3; h++) {
        float sl, sh, t0l, t0h, t1l, t1h;
        UPK(sl, sh, S[h]); UPK(t0l, t0h, T0[h]); UPK(t1l, t1h, T1[h]);
        float Sv = sl + sh, T0v = t0l + t0h, T1v = t1l + t1h;
        acc[h*4+0] = Sv;
        acc[h*4+1] = T0v;
        acc[h*4+2] = T1v;
        acc[h*4+3] = -(T0v + T1v);
    }
    #pragma unroll
    for (int f = 0; f < 12; f++) {
        float vv = acc[f];
        #pragma unroll
        for (int off = 16; off > 0; off >>= 1)
            vv += __shfl_xor_sync(0xffffffffu, vv, off);
        acc[f] = vv;
    }
    if (lane == 0) {
        #pragma unroll
        for (int f = 0; f < 12; f++) s_red[warp][f] = acc[f];
    }
    __syncthreads();
    if (t < 12) {
        float vv = 0.f;
        #pragma unroll
        for (int w = 0; w < NWARP; w++) vv += s_red[w][t];
        g_fast[b][blk][t] = vv;
    }
    __threadfence();
    if (t == 0) s_win = (atomicAdd(&g_cnt[b], 1) == BPB - 1);
    __syncthreads();
    if (!s_win) return;

    // winner: combine 37 partials per head, o[h] = SV/S
    if (warp < 3) {
        float r0 = 0.f, r1 = 0.f, r2 = 0.f, r3 = 0.f;
        {
            float4 p = __ldcg((const float4*)&g_fast[b][lane][warp*4]);
            r0 = p.x; r1 = p.y; r2 = p.z; r3 = p.w;
        }
        if (lane + 32 < BPB) {
            float4 p = __ldcg((const float4*)&g_fast[b][lane+32][warp*4]);
            r0 += p.x; r1 += p.y; r2 += p.z; r3 += p.w;
        }
        #pragma unroll
        for (int off = 16; off > 0; off >>= 1) {
            r0 += __shfl_xor_sync(0xffffffffu, r0, off);
            r1 += __shfl_xor_sync(0xffffffffu, r1, off);
            r2 += __shfl_xor_sync(0xffffffffu, r2, off);
            r3 += __shfl_xor_sync(0xffffffffu, r3, off);
        }
        if (lane == 0) {
            int h = warp;
            float Bvh = bv[h];
            float Av0 = Wv[h*3+0] * ln1w[0];
            float Av1 = Wv[h*3+1] * ln1w[1];
            float Av2 = Wv[h*3+2] * ln1w[2];
            #pragma unroll
            for (int c = 0; c < 3; c++) Bvh += Wv[h*3+c] * ln1b[c];
            float SV = Bvh*r0 + Av0*r1 + Av1*r2 + Av2*r3;
            s_o[h] = SV / r0;
        }
    }
    __syncthreads();
    if (t == 0) {
        g_cnt[b] = 0;   // reset for next graph replay
        epilogue_one(b, 0, s_o[0], s_o[1], s_o[2], Wp, bp, ln2w, ln2b,
                     W1, b1, W2, b2, Wg, bg, Wc, bc, gb, cb, out);
        // fast path: all 10 query rows identical; rows 1..9 share one y
        // recompute colbase cheaply via epilogue_one's math inline:
    }
    if (t == 1) {
        // rows 1..9 (all identical y): compute once, fan out
        float o0 = s_o[0], o1 = s_o[1], o2 = s_o[2];
        float op[3];
        #pragma unroll
        for (int e = 0; e < 3; e++)
            op[e] = bp[e] + o0*Wp[e*3+0] + o1*Wp[e*3+1] + o2*Wp[e*3+2];
        float mu = (op[0] + op[1] + op[2]) * (1.0f/3.0f);
        float d0 = op[0]-mu, d1 = op[1]-mu, d2 = op[2]-mu;
        float var = (d0*d0 + d1*d1 + d2*d2) * (1.0f/3.0f);
        float inv = rsqrtf(var + EPS);
        float h2[3];
        h2[0] = d0*inv*ln2w[0] + ln2b[0];
        h2[1] = d1*inv*ln2w[1] + ln2b[1];
        h2[2] = d2*inv*ln2w[2] + ln2b[2];
        float y[3] = { op[0] + b2[0], op[1] + b2[1], op[2] + b2[2] };
        #pragma unroll
        for (int f = 0; f < 12; f++) {
            float u = b1[f] + h2[0]*W1[f*3+0] + h2[1]*W1[f*3+1] + h2[2]*W1[f*3+2];
            float su = u / (1.0f + __expf(-u));
            y[0] += su * W2[0*12 + f];
            y[1] += su * W2[1*12 + f];
            y[2] += su * W2[2*12 + f];
        }
        float colbase = bc[0] + y[0]*Wc[0] + y[1]*Wc[1] + y[2]*Wc[2];
        #pragma unroll
        for (int p = 0; p < 9; p++)
            out[NB + b*9 + p] = colbase + cb[p];
    }
}

extern "C" void kernel_launch(void* const* d_in, const int* in_sizes, int n_in,
                              void* d_out, int out_size)
{
    const float* x    = (const float*)d_in[0];
    const float* qp   = (const float*)d_in[1];
    const float* ln1w = (const float*)d_in[2];
    const float* ln1b = (const float*)d_in[3];
    const float* Wk   = (const float*)d_in[4];
    const float* bk   = (const float*)d_in[5];
    const float* Wv   = (const float*)d_in[6];
    const float* bv   = (const float*)d_in[7];
    const float* Wp   = (const float*)d_in[8];
    const float* bp   = (const float*)d_in[9];
    const float* ln2w = (const float*)d_in[10];
    const float* ln2b = (const float*)d_in[11];
    const float* W1   = (const float*)d_in[12];
    const float* b1   = (const float*)d_in[13];
    const float* W2   = (const float*)d_in[14];
    const float* b2   = (const float*)d_in[15];
    const float* Wg   = (const float*)d_in[16];
    const float* bg   = (const float*)d_in[17];
    const float* Wc   = (const float*)d_in[18];
    const float* bc   = (const float*)d_in[19];
    const float* gb   = (const float*)d_in[20];
    const float* cb   = (const float*)d_in[21];
    float* out = (float*)d_out;

    k_all<<<NB*BPB, THREADS>>>(x, qp, ln1w, ln1b, Wk, bk, Wv, bv,
                               Wp, bp, ln2w, ln2b, W1, b1, W2, b2,
                               Wg, bg, Wc, bc, gb, cb, out);
}